// round 1
// baseline (speedup 1.0000x reference)
#include <cuda_runtime.h>
#include <cuda_bf16.h>

// Problem constants
#define Bq 4
#define Sq 2048
#define Eq 1024
#define Hq 16
#define Dq 64
// 3E = 3072

// Scratch buffers (allocation-free rule: use __device__ globals)
__device__ float g_qkv[(size_t)Bq * Sq * 3 * Eq]; // [b,s, c*1024 + h*64 + d], 96 MB
__device__ float g_ctx[(size_t)Bq * Sq * Eq];     // [b,s, h*64 + d], 32 MB

// ---------------------------------------------------------------------------
// SGEMM: C[M,N] = A[M,K] * B[N,K]^T + bias[N]   (both A and B row-major, K-contig)
// 128x128 tile, BK=8, 256 threads, 8x8 per thread.
// ---------------------------------------------------------------------------
#define BM 128
#define BN 128
#define BK 8

__global__ __launch_bounds__(256) void sgemm_abt(const float* __restrict__ A,
                                                 const float* __restrict__ B,
                                                 const float* __restrict__ bias,
                                                 float* __restrict__ C,
                                                 int M, int N, int K)
{
    __shared__ float As[BK][BM + 4];
    __shared__ float Bs[BK][BN + 4];

    const int t  = threadIdx.x;
    const int tx = t & 15;       // 0..15
    const int ty = t >> 4;       // 0..15
    const int m0 = blockIdx.y * BM;
    const int n0 = blockIdx.x * BN;

    const int lr = t >> 1;        // 0..127 (tile row to load)
    const int lc = (t & 1) * 4;   // 0 or 4 (k-offset within BK)

    const float* Ab = A + (long)m0 * K;
    const float* Bb = B + (long)n0 * K;

    float acc[8][8];
#pragma unroll
    for (int i = 0; i < 8; i++)
#pragma unroll
        for (int j = 0; j < 8; j++) acc[i][j] = 0.f;

    for (int k0 = 0; k0 < K; k0 += BK) {
        float4 av = *(const float4*)(Ab + (long)lr * K + k0 + lc);
        float4 bv = *(const float4*)(Bb + (long)lr * K + k0 + lc);
        __syncthreads();   // previous compute done before overwriting smem
        As[lc + 0][lr] = av.x; As[lc + 1][lr] = av.y;
        As[lc + 2][lr] = av.z; As[lc + 3][lr] = av.w;
        Bs[lc + 0][lr] = bv.x; Bs[lc + 1][lr] = bv.y;
        Bs[lc + 2][lr] = bv.z; Bs[lc + 3][lr] = bv.w;
        __syncthreads();

#pragma unroll
        for (int kk = 0; kk < BK; kk++) {
            float a[8], b[8];
            float4 a0 = *(const float4*)&As[kk][ty * 8];
            float4 a1 = *(const float4*)&As[kk][ty * 8 + 4];
            float4 b0 = *(const float4*)&Bs[kk][tx * 8];
            float4 b1 = *(const float4*)&Bs[kk][tx * 8 + 4];
            a[0]=a0.x; a[1]=a0.y; a[2]=a0.z; a[3]=a0.w;
            a[4]=a1.x; a[5]=a1.y; a[6]=a1.z; a[7]=a1.w;
            b[0]=b0.x; b[1]=b0.y; b[2]=b0.z; b[3]=b0.w;
            b[4]=b1.x; b[5]=b1.y; b[6]=b1.z; b[7]=b1.w;
#pragma unroll
            for (int i = 0; i < 8; i++)
#pragma unroll
                for (int j = 0; j < 8; j++)
                    acc[i][j] += a[i] * b[j];
        }
    }

#pragma unroll
    for (int i = 0; i < 8; i++) {
        const long row = (long)(m0 + ty * 8 + i) * N + n0 + tx * 8;
#pragma unroll
        for (int j = 0; j < 8; j += 4) {
            float4 o;
            o.x = acc[i][j + 0] + bias[n0 + tx * 8 + j + 0];
            o.y = acc[i][j + 1] + bias[n0 + tx * 8 + j + 1];
            o.z = acc[i][j + 2] + bias[n0 + tx * 8 + j + 2];
            o.w = acc[i][j + 3] + bias[n0 + tx * 8 + j + 3];
            *(float4*)(C + row + j) = o;
        }
    }
}

// ---------------------------------------------------------------------------
// Flash-style fp32 attention. grid = (S/128, B*H), block = 128 threads.
// Each thread owns one query row: q[64] in regs, acc[64] in regs,
// online softmax over 16-key tiles staged in shared memory.
// ---------------------------------------------------------------------------
#define QT 128
#define KT 16

__global__ __launch_bounds__(128) void attn_kernel(const float* __restrict__ qkv,
                                                   float* __restrict__ ctx)
{
    __shared__ float4 Ks[KT][16];  // [key][d/4]
    __shared__ float4 Vs[KT][16];

    const int bh = blockIdx.y;
    const int b  = bh >> 4;       // /H
    const int h  = bh & 15;       // %H
    const int t  = threadIdx.x;
    const int q  = blockIdx.x * QT + t;
    const float scale = 0.125f;   // 1/sqrt(64)

    // load query (c=0 slice)
    const long qoff = ((long)(b * Sq + q)) * 3072 + h * 64;
    float4 qv[16];
#pragma unroll
    for (int i = 0; i < 16; i++) qv[i] = *(const float4*)(qkv + qoff + 4 * i);

    float4 acc[16];
#pragma unroll
    for (int i = 0; i < 16; i++) acc[i] = make_float4(0.f, 0.f, 0.f, 0.f);
    float mval = -1e30f, l = 0.f;

    for (int kt = 0; kt < Sq; kt += KT) {
        __syncthreads();
        // load KT keys + values: 256 float4 each -> 2 per thread per tensor
#pragma unroll
        for (int i = 0; i < 2; i++) {
            int slot = t * 2 + i;            // 0..255
            int j  = slot >> 4;              // key within tile
            int d4 = slot & 15;              // float4 within head dim
            long base = ((long)(b * Sq + kt + j)) * 3072 + h * 64 + d4 * 4;
            Ks[j][d4] = *(const float4*)(qkv + base + 1024);
            Vs[j][d4] = *(const float4*)(qkv + base + 2048);
        }
        __syncthreads();

        float s[KT];
        float tmax = -1e30f;
#pragma unroll
        for (int j = 0; j < KT; j++) {
            float sj = 0.f;
#pragma unroll
            for (int d4 = 0; d4 < 16; d4++) {
                float4 kv = Ks[j][d4];
                sj += qv[d4].x * kv.x + qv[d4].y * kv.y
                    + qv[d4].z * kv.z + qv[d4].w * kv.w;
            }
            sj *= scale;
            s[j] = sj;
            tmax = fmaxf(tmax, sj);
        }

        float mnew = fmaxf(mval, tmax);
        float corr = __expf(mval - mnew);
        l *= corr;
#pragma unroll
        for (int i = 0; i < 16; i++) {
            acc[i].x *= corr; acc[i].y *= corr;
            acc[i].z *= corr; acc[i].w *= corr;
        }
#pragma unroll
        for (int j = 0; j < KT; j++) {
            float p = __expf(s[j] - mnew);
            l += p;
#pragma unroll
            for (int d4 = 0; d4 < 16; d4++) {
                float4 vv = Vs[j][d4];
                acc[d4].x += p * vv.x; acc[d4].y += p * vv.y;
                acc[d4].z += p * vv.z; acc[d4].w += p * vv.w;
            }
        }
        mval = mnew;
    }

    const float inv = 1.0f / l;
    const long coff = ((long)(b * Sq + q)) * Eq + h * 64;
#pragma unroll
    for (int i = 0; i < 16; i++) {
        float4 o;
        o.x = acc[i].x * inv; o.y = acc[i].y * inv;
        o.z = acc[i].z * inv; o.w = acc[i].w * inv;
        *(float4*)(ctx + coff + 4 * i) = o;
    }
}

// ---------------------------------------------------------------------------
// Launch
// ---------------------------------------------------------------------------
extern "C" void kernel_launch(void* const* d_in, const int* in_sizes, int n_in,
                              void* d_out, int out_size)
{
    const float* inp   = (const float*)d_in[0];
    const float* qkv_w = (const float*)d_in[1];
    const float* qkv_b = (const float*)d_in[2];
    const float* out_w = (const float*)d_in[3];
    const float* out_b = (const float*)d_in[4];
    float* out = (float*)d_out;

    float* qkv_buf = nullptr;
    float* ctx_buf = nullptr;
    cudaGetSymbolAddress((void**)&qkv_buf, g_qkv);
    cudaGetSymbolAddress((void**)&ctx_buf, g_ctx);

    const int M = Bq * Sq;          // 8192
    // 1) QKV projection: [8192,1024] x [3072,1024]^T -> [8192,3072]
    {
        dim3 grid(3 * Eq / BN, M / BM);   // (24, 64)
        sgemm_abt<<<grid, 256>>>(inp, qkv_w, qkv_b, qkv_buf, M, 3 * Eq, Eq);
    }
    // 2) Attention
    {
        dim3 grid(Sq / QT, Bq * Hq);      // (16, 64)
        attn_kernel<<<grid, 128>>>(qkv_buf, ctx_buf);
    }
    // 3) Output projection: [8192,1024] x [1024,1024]^T -> [8192,1024]
    {
        dim3 grid(Eq / BN, M / BM);       // (8, 64)
        sgemm_abt<<<grid, 256>>>(ctx_buf, out_w, out_b, out, M, Eq, Eq);
    }
}

// round 3
// speedup vs baseline: 1.1353x; 1.1353x over previous
#include <cuda_runtime.h>
#include <cuda_bf16.h>
#include <cstdint>

#define Bq 4
#define Sq 2048
#define Eq 1024
#define Hq 16

// Scratch (allocation-free rule)
__device__ float g_qkv[(size_t)Bq * Sq * 3 * Eq]; // [b,s, c*1024 + h*64 + d]
__device__ float g_ctx[(size_t)Bq * Sq * Eq];

// ---------------------------------------------------------------------------
// mma.sync helpers (non-'a' ISA: works on compute_103 target)
// ---------------------------------------------------------------------------
__device__ __forceinline__ uint32_t smem_u32(const void* p) {
    uint32_t a;
    asm("{ .reg .u64 t; cvta.to.shared.u64 t, %1; cvt.u32.u64 %0, t; }"
        : "=r"(a) : "l"(p));
    return a;
}

#define LDMX4(r0, r1, r2, r3, addr)                                         \
    asm volatile("ldmatrix.sync.aligned.m8n8.x4.shared.b16 {%0,%1,%2,%3}, [%4];" \
                 : "=r"(r0), "=r"(r1), "=r"(r2), "=r"(r3) : "r"(addr))

__device__ __forceinline__ void mma_bf16(float* c,
                                         uint32_t a0, uint32_t a1, uint32_t a2, uint32_t a3,
                                         uint32_t b0, uint32_t b1) {
    asm volatile("mma.sync.aligned.m16n8k16.row.col.f32.bf16.bf16.f32 "
                 "{%0,%1,%2,%3}, {%4,%5,%6,%7}, {%8,%9}, {%0,%1,%2,%3};"
                 : "+f"(c[0]), "+f"(c[1]), "+f"(c[2]), "+f"(c[3])
                 : "r"(a0), "r"(a1), "r"(a2), "r"(a3), "r"(b0), "r"(b1));
}

// split fp32 -> (hi, lo) bf16 pair packed helpers
__device__ __forceinline__ void split4(float4 v, uint2& hp, uint2& lp) {
    __nv_bfloat16 h0 = __float2bfloat16(v.x), h1 = __float2bfloat16(v.y);
    __nv_bfloat16 h2 = __float2bfloat16(v.z), h3 = __float2bfloat16(v.w);
    __nv_bfloat16 l0 = __float2bfloat16(v.x - __bfloat162float(h0));
    __nv_bfloat16 l1 = __float2bfloat16(v.y - __bfloat162float(h1));
    __nv_bfloat16 l2 = __float2bfloat16(v.z - __bfloat162float(h2));
    __nv_bfloat16 l3 = __float2bfloat16(v.w - __bfloat162float(h3));
    hp.x = (uint32_t)__bfloat16_as_ushort(h0) | ((uint32_t)__bfloat16_as_ushort(h1) << 16);
    hp.y = (uint32_t)__bfloat16_as_ushort(h2) | ((uint32_t)__bfloat16_as_ushort(h3) << 16);
    lp.x = (uint32_t)__bfloat16_as_ushort(l0) | ((uint32_t)__bfloat16_as_ushort(l1) << 16);
    lp.y = (uint32_t)__bfloat16_as_ushort(l2) | ((uint32_t)__bfloat16_as_ushort(l3) << 16);
}

// ---------------------------------------------------------------------------
// Split-bf16 HMMA GEMM: C[M,N] = A[M,K]*B[N,K]^T + bias[N]  (fp32 in/out)
// 128x128 CTA tile, 8 warps (2x4), warp tile 64x32, K-chunk 32 fp32.
// 3-term emulation: hi*hi + hi*lo + lo*hi, fp32 accumulate.
// ---------------------------------------------------------------------------
#define BM 128
#define BN 128
#define BKc 32
#define RS 40   // smem row stride (bf16 elems): 32 + 8 pad -> conflict-free ldmatrix

__global__ __launch_bounds__(256, 1) void gemm_mma(const float* __restrict__ A,
                                                   const float* __restrict__ B,
                                                   const float* __restrict__ bias,
                                                   float* __restrict__ C,
                                                   int M, int N, int K)
{
    __shared__ __nv_bfloat16 Ah[BM * RS], Al[BM * RS];
    __shared__ __nv_bfloat16 Bh[BN * RS], Bl[BN * RS];

    const int t   = threadIdx.x;
    const int wid = t >> 5;
    const int ln  = t & 31;
    const int m0  = blockIdx.y * BM;
    const int n0  = blockIdx.x * BN;
    const int wm  = (wid >> 2) * 64;  // warp m offset
    const int wn  = (wid & 3) * 32;   // warp n offset

    const float* Abase = A + (size_t)m0 * K;
    const float* Bbase = B + (size_t)n0 * K;

    float acc[4][4][4];
#pragma unroll
    for (int i = 0; i < 4; i++)
#pragma unroll
        for (int j = 0; j < 4; j++)
#pragma unroll
            for (int f = 0; f < 4; f++) acc[i][j][f] = 0.f;

    // ldmatrix base addresses (per-lane), in bytes
    const uint32_t sAh = smem_u32(Ah), sAl = smem_u32(Al);
    const uint32_t sBh = smem_u32(Bh), sBl = smem_u32(Bl);
    const int lrow = (ln & 7) + ((ln >> 3) & 1) * 8;  // row within 16-row tile
    const int lkc  = (ln >> 4) * 8;                    // k col offset (0 or 8)

    const int NC = K / BKc;
    float4 av[4], bv[4];

    // prefetch chunk 0
#pragma unroll
    for (int i = 0; i < 4; i++) {
        int idx = i * 256 + t;
        int row = idx >> 3, c4 = idx & 7;
        av[i] = *(const float4*)(Abase + (size_t)row * K + c4 * 4);
        bv[i] = *(const float4*)(Bbase + (size_t)row * K + c4 * 4);
    }

    for (int kc = 0; kc < NC; kc++) {
        __syncthreads();
#pragma unroll
        for (int i = 0; i < 4; i++) {
            int idx = i * 256 + t;
            int row = idx >> 3, c4 = idx & 7;
            uint2 hp, lp;
            split4(av[i], hp, lp);
            *(uint2*)&Ah[row * RS + c4 * 4] = hp;
            *(uint2*)&Al[row * RS + c4 * 4] = lp;
            split4(bv[i], hp, lp);
            *(uint2*)&Bh[row * RS + c4 * 4] = hp;
            *(uint2*)&Bl[row * RS + c4 * 4] = lp;
        }
        __syncthreads();

        // prefetch next chunk while computing this one
        if (kc + 1 < NC) {
            const int k0n = (kc + 1) * BKc;
#pragma unroll
            for (int i = 0; i < 4; i++) {
                int idx = i * 256 + t;
                int row = idx >> 3, c4 = idx & 7;
                av[i] = *(const float4*)(Abase + (size_t)row * K + k0n + c4 * 4);
                bv[i] = *(const float4*)(Bbase + (size_t)row * K + k0n + c4 * 4);
            }
        }

#pragma unroll
        for (int ks = 0; ks < 2; ks++) {
            const int kb = ks * 16;
            uint32_t ah[4][4], al[4][4], bh[2][4], bl[2][4];
#pragma unroll
            for (int i = 0; i < 4; i++) {
                uint32_t ra = (uint32_t)(((wm + i * 16 + lrow) * RS + kb + lkc) * 2);
                LDMX4(ah[i][0], ah[i][1], ah[i][2], ah[i][3], sAh + ra);
            }
#pragma unroll
            for (int j = 0; j < 2; j++) {
                uint32_t rb = (uint32_t)(((wn + j * 16 + lrow) * RS + kb + lkc) * 2);
                LDMX4(bh[j][0], bh[j][1], bh[j][2], bh[j][3], sBh + rb);
            }
            // hi * hi
#pragma unroll
            for (int i = 0; i < 4; i++)
#pragma unroll
                for (int j = 0; j < 4; j++)
                    mma_bf16(acc[i][j], ah[i][0], ah[i][1], ah[i][2], ah[i][3],
                             bh[j >> 1][j & 1], bh[j >> 1][2 + (j & 1)]);
            // hi * lo
#pragma unroll
            for (int j = 0; j < 2; j++) {
                uint32_t rb = (uint32_t)(((wn + j * 16 + lrow) * RS + kb + lkc) * 2);
                LDMX4(bl[j][0], bl[j][1], bl[j][2], bl[j][3], sBl + rb);
            }
#pragma unroll
            for (int i = 0; i < 4; i++)
#pragma unroll
                for (int j = 0; j < 4; j++)
                    mma_bf16(acc[i][j], ah[i][0], ah[i][1], ah[i][2], ah[i][3],
                             bl[j >> 1][j & 1], bl[j >> 1][2 + (j & 1)]);
            // lo * hi
#pragma unroll
            for (int i = 0; i < 4; i++) {
                uint32_t ra = (uint32_t)(((wm + i * 16 + lrow) * RS + kb + lkc) * 2);
                LDMX4(al[i][0], al[i][1], al[i][2], al[i][3], sAl + ra);
            }
#pragma unroll
            for (int i = 0; i < 4; i++)
#pragma unroll
                for (int j = 0; j < 4; j++)
                    mma_bf16(acc[i][j], al[i][0], al[i][1], al[i][2], al[i][3],
                             bh[j >> 1][j & 1], bh[j >> 1][2 + (j & 1)]);
        }
    }

    // Epilogue: c0,c1 at row r; c2,c3 at row r+8; cols (ln&3)*2, +1
    const int er = ln >> 2;
    const int ec = (ln & 3) * 2;
#pragma unroll
    for (int i = 0; i < 4; i++) {
#pragma unroll
        for (int j = 0; j < 4; j++) {
            const int col = n0 + wn + j * 8 + ec;
            const float b0 = __ldg(bias + col), b1 = __ldg(bias + col + 1);
            const int r0 = m0 + wm + i * 16 + er;
            float2 o0 = make_float2(acc[i][j][0] + b0, acc[i][j][1] + b1);
            float2 o1 = make_float2(acc[i][j][2] + b0, acc[i][j][3] + b1);
            *(float2*)(C + (size_t)r0 * N + col) = o0;
            *(float2*)(C + (size_t)(r0 + 8) * N + col) = o1;
        }
    }
}

// ---------------------------------------------------------------------------
// Flash-style fp32 attention (unchanged, proven).
// ---------------------------------------------------------------------------
#define QT 128
#define KT 16

__global__ __launch_bounds__(128) void attn_kernel(const float* __restrict__ qkv,
                                                   float* __restrict__ ctx)
{
    __shared__ float4 Ks[KT][16];
    __shared__ float4 Vs[KT][16];

    const int bh = blockIdx.y;
    const int b = bh >> 4;
    const int h = bh & 15;
    const int t = threadIdx.x;
    const int q = blockIdx.x * QT + t;
    const float scale = 0.125f;

    const long qoff = ((long)(b * Sq + q)) * 3072 + h * 64;
    float4 qv[16];
#pragma unroll
    for (int i = 0; i < 16; i++) qv[i] = *(const float4*)(qkv + qoff + 4 * i);

    float4 acc[16];
#pragma unroll
    for (int i = 0; i < 16; i++) acc[i] = make_float4(0.f, 0.f, 0.f, 0.f);
    float mval = -1e30f, l = 0.f;

    for (int kt = 0; kt < Sq; kt += KT) {
        __syncthreads();
#pragma unroll
        for (int i = 0; i < 2; i++) {
            int slot = t * 2 + i;
            int j = slot >> 4;
            int d4 = slot & 15;
            long base = ((long)(b * Sq + kt + j)) * 3072 + h * 64 + d4 * 4;
            Ks[j][d4] = *(const float4*)(qkv + base + 1024);
            Vs[j][d4] = *(const float4*)(qkv + base + 2048);
        }
        __syncthreads();

        float s[KT];
        float tmax = -1e30f;
#pragma unroll
        for (int j = 0; j < KT; j++) {
            float sj = 0.f;
#pragma unroll
            for (int d4 = 0; d4 < 16; d4++) {
                float4 kv = Ks[j][d4];
                sj += qv[d4].x * kv.x + qv[d4].y * kv.y
                    + qv[d4].z * kv.z + qv[d4].w * kv.w;
            }
            sj *= scale;
            s[j] = sj;
            tmax = fmaxf(tmax, sj);
        }

        float mnew = fmaxf(mval, tmax);
        float corr = __expf(mval - mnew);
        l *= corr;
#pragma unroll
        for (int i = 0; i < 16; i++) {
            acc[i].x *= corr; acc[i].y *= corr;
            acc[i].z *= corr; acc[i].w *= corr;
        }
#pragma unroll
        for (int j = 0; j < KT; j++) {
            float p = __expf(s[j] - mnew);
            l += p;
#pragma unroll
            for (int d4 = 0; d4 < 16; d4++) {
                float4 vv = Vs[j][d4];
                acc[d4].x += p * vv.x; acc[d4].y += p * vv.y;
                acc[d4].z += p * vv.z; acc[d4].w += p * vv.w;
            }
        }
        mval = mnew;
    }

    const float inv = 1.0f / l;
    const long coff = ((long)(b * Sq + q)) * Eq + h * 64;
#pragma unroll
    for (int i = 0; i < 16; i++) {
        float4 o;
        o.x = acc[i].x * inv; o.y = acc[i].y * inv;
        o.z = acc[i].z * inv; o.w = acc[i].w * inv;
        *(float4*)(ctx + coff + 4 * i) = o;
    }
}

// ---------------------------------------------------------------------------
// Launch
// ---------------------------------------------------------------------------
extern "C" void kernel_launch(void* const* d_in, const int* in_sizes, int n_in,
                              void* d_out, int out_size)
{
    const float* inp   = (const float*)d_in[0];
    const float* qkv_w = (const float*)d_in[1];
    const float* qkv_b = (const float*)d_in[2];
    const float* out_w = (const float*)d_in[3];
    const float* out_b = (const float*)d_in[4];
    float* out = (float*)d_out;

    float* qkv_buf = nullptr;
    float* ctx_buf = nullptr;
    cudaGetSymbolAddress((void**)&qkv_buf, g_qkv);
    cudaGetSymbolAddress((void**)&ctx_buf, g_ctx);

    const int M = Bq * Sq; // 8192

    // 1) QKV projection: [8192,1024] x [3072,1024]^T -> [8192,3072]
    {
        dim3 grid(3 * Eq / BN, M / BM); // (24, 64)
        gemm_mma<<<grid, 256>>>(inp, qkv_w, qkv_b, qkv_buf, M, 3 * Eq, Eq);
    }
    // 2) Attention
    {
        dim3 grid(Sq / QT, Bq * Hq); // (16, 64)
        attn_kernel<<<grid, 128>>>(qkv_buf, ctx_buf);
    }
    // 3) Output projection: [8192,1024] x [1024,1024]^T -> [8192,1024]
    {
        dim3 grid(Eq / BN, M / BM); // (8, 64)
        gemm_mma<<<grid, 256>>>(ctx_buf, out_w, out_b, out, M, Eq, Eq);
    }
}

// round 10
// speedup vs baseline: 2.4207x; 2.1322x over previous
#include <cuda_runtime.h>
#include <cuda_bf16.h>
#include <cuda_fp16.h>
#include <cstdint>

#define Bq 4
#define Sq 2048
#define Eq 1024
#define Hq 16

// Scratch (allocation-free rule)
__device__ float g_qkv[(size_t)Bq * Sq * 3 * Eq]; // [b,s, c*1024 + h*64 + d]
__device__ float g_ctx[(size_t)Bq * Sq * Eq];

// ---------------------------------------------------------------------------
// mma.sync helpers
// ---------------------------------------------------------------------------
__device__ __forceinline__ uint32_t smem_u32(const void* p) {
    uint32_t a;
    asm("{ .reg .u64 t; cvta.to.shared.u64 t, %1; cvt.u32.u64 %0, t; }"
        : "=r"(a) : "l"(p));
    return a;
}

#define LDMX4(r0, r1, r2, r3, addr)                                         \
    asm volatile("ldmatrix.sync.aligned.m8n8.x4.shared.b16 {%0,%1,%2,%3}, [%4];" \
                 : "=r"(r0), "=r"(r1), "=r"(r2), "=r"(r3) : "r"(addr))

__device__ __forceinline__ void mma_bf16(float* c, const uint32_t* a,
                                         uint32_t b0, uint32_t b1) {
    asm volatile("mma.sync.aligned.m16n8k16.row.col.f32.bf16.bf16.f32 "
                 "{%0,%1,%2,%3}, {%4,%5,%6,%7}, {%8,%9}, {%0,%1,%2,%3};"
                 : "+f"(c[0]), "+f"(c[1]), "+f"(c[2]), "+f"(c[3])
                 : "r"(a[0]), "r"(a[1]), "r"(a[2]), "r"(a[3]), "r"(b0), "r"(b1));
}

__device__ __forceinline__ void mma_f16(float* c, const uint32_t* a,
                                        uint32_t b0, uint32_t b1) {
    asm volatile("mma.sync.aligned.m16n8k16.row.col.f32.f16.f16.f32 "
                 "{%0,%1,%2,%3}, {%4,%5,%6,%7}, {%8,%9}, {%0,%1,%2,%3};"
                 : "+f"(c[0]), "+f"(c[1]), "+f"(c[2]), "+f"(c[3])
                 : "r"(a[0]), "r"(a[1]), "r"(a[2]), "r"(a[3]), "r"(b0), "r"(b1));
}

// split fp32 -> (hi, lo) bf16 packed
__device__ __forceinline__ void split4(float4 v, uint2& hp, uint2& lp) {
    __nv_bfloat16 h0 = __float2bfloat16(v.x), h1 = __float2bfloat16(v.y);
    __nv_bfloat16 h2 = __float2bfloat16(v.z), h3 = __float2bfloat16(v.w);
    __nv_bfloat16 l0 = __float2bfloat16(v.x - __bfloat162float(h0));
    __nv_bfloat16 l1 = __float2bfloat16(v.y - __bfloat162float(h1));
    __nv_bfloat16 l2 = __float2bfloat16(v.z - __bfloat162float(h2));
    __nv_bfloat16 l3 = __float2bfloat16(v.w - __bfloat162float(h3));
    hp.x = (uint32_t)__bfloat16_as_ushort(h0) | ((uint32_t)__bfloat16_as_ushort(h1) << 16);
    hp.y = (uint32_t)__bfloat16_as_ushort(h2) | ((uint32_t)__bfloat16_as_ushort(h3) << 16);
    lp.x = (uint32_t)__bfloat16_as_ushort(l0) | ((uint32_t)__bfloat16_as_ushort(l1) << 16);
    lp.y = (uint32_t)__bfloat16_as_ushort(l2) | ((uint32_t)__bfloat16_as_ushort(l3) << 16);
}

// fast exp2 on FMA pipe (arg <= 0 expected), rel err ~2e-6
__device__ __forceinline__ float exp2_fast(float y) {
    y = fmaxf(y, -60.0f);
    int e = __float2int_rn(y);
    float f = y - __int2float_rn(e);               // f in [-0.5, 0.5]
    float p = 1.3333558e-3f;
    p = fmaf(p, f, 9.6181291e-3f);
    p = fmaf(p, f, 5.5504109e-2f);
    p = fmaf(p, f, 2.4022651e-1f);
    p = fmaf(p, f, 6.9314718e-1f);
    p = fmaf(p, f, 1.0f);
    return __int_as_float((e + 127) << 23) * p;
}

// ---------------------------------------------------------------------------
// Split-bf16 HMMA GEMM: C = A*B^T + bias (proven round 3, unchanged)
// ---------------------------------------------------------------------------
#define BM 128
#define BN 128
#define BKc 32
#define RS 40

__global__ __launch_bounds__(256, 1) void gemm_mma(const float* __restrict__ A,
                                                   const float* __restrict__ B,
                                                   const float* __restrict__ bias,
                                                   float* __restrict__ C,
                                                   int M, int N, int K)
{
    __shared__ __nv_bfloat16 Ah[BM * RS], Al[BM * RS];
    __shared__ __nv_bfloat16 Bh[BN * RS], Bl[BN * RS];

    const int t   = threadIdx.x;
    const int wid = t >> 5;
    const int ln  = t & 31;
    const int m0  = blockIdx.y * BM;
    const int n0  = blockIdx.x * BN;
    const int wm  = (wid >> 2) * 64;
    const int wn  = (wid & 3) * 32;

    const float* Abase = A + (size_t)m0 * K;
    const float* Bbase = B + (size_t)n0 * K;

    float acc[4][4][4];
#pragma unroll
    for (int i = 0; i < 4; i++)
#pragma unroll
        for (int j = 0; j < 4; j++)
#pragma unroll
            for (int f = 0; f < 4; f++) acc[i][j][f] = 0.f;

    const uint32_t sAh = smem_u32(Ah), sAl = smem_u32(Al);
    const uint32_t sBh = smem_u32(Bh), sBl = smem_u32(Bl);
    const int lrow = (ln & 7) + ((ln >> 3) & 1) * 8;
    const int lkc  = (ln >> 4) * 8;

    const int NC = K / BKc;
    float4 av[4], bv[4];

#pragma unroll
    for (int i = 0; i < 4; i++) {
        int idx = i * 256 + t;
        int row = idx >> 3, c4 = idx & 7;
        av[i] = *(const float4*)(Abase + (size_t)row * K + c4 * 4);
        bv[i] = *(const float4*)(Bbase + (size_t)row * K + c4 * 4);
    }

    for (int kc = 0; kc < NC; kc++) {
        __syncthreads();
#pragma unroll
        for (int i = 0; i < 4; i++) {
            int idx = i * 256 + t;
            int row = idx >> 3, c4 = idx & 7;
            uint2 hp, lp;
            split4(av[i], hp, lp);
            *(uint2*)&Ah[row * RS + c4 * 4] = hp;
            *(uint2*)&Al[row * RS + c4 * 4] = lp;
            split4(bv[i], hp, lp);
            *(uint2*)&Bh[row * RS + c4 * 4] = hp;
            *(uint2*)&Bl[row * RS + c4 * 4] = lp;
        }
        __syncthreads();

        if (kc + 1 < NC) {
            const int k0n = (kc + 1) * BKc;
#pragma unroll
            for (int i = 0; i < 4; i++) {
                int idx = i * 256 + t;
                int row = idx >> 3, c4 = idx & 7;
                av[i] = *(const float4*)(Abase + (size_t)row * K + k0n + c4 * 4);
                bv[i] = *(const float4*)(Bbase + (size_t)row * K + k0n + c4 * 4);
            }
        }

#pragma unroll
        for (int ks = 0; ks < 2; ks++) {
            const int kb = ks * 16;
            uint32_t ah[4][4], al[4][4], bh[2][4], bl[2][4];
#pragma unroll
            for (int i = 0; i < 4; i++) {
                uint32_t ra = (uint32_t)(((wm + i * 16 + lrow) * RS + kb + lkc) * 2);
                LDMX4(ah[i][0], ah[i][1], ah[i][2], ah[i][3], sAh + ra);
            }
#pragma unroll
            for (int j = 0; j < 2; j++) {
                uint32_t rb = (uint32_t)(((wn + j * 16 + lrow) * RS + kb + lkc) * 2);
                LDMX4(bh[j][0], bh[j][1], bh[j][2], bh[j][3], sBh + rb);
            }
#pragma unroll
            for (int i = 0; i < 4; i++)
#pragma unroll
                for (int j = 0; j < 4; j++)
                    mma_bf16(acc[i][j], ah[i], bh[j >> 1][j & 1], bh[j >> 1][2 + (j & 1)]);
#pragma unroll
            for (int j = 0; j < 2; j++) {
                uint32_t rb = (uint32_t)(((wn + j * 16 + lrow) * RS + kb + lkc) * 2);
                LDMX4(bl[j][0], bl[j][1], bl[j][2], bl[j][3], sBl + rb);
            }
#pragma unroll
            for (int i = 0; i < 4; i++)
#pragma unroll
                for (int j = 0; j < 4; j++)
                    mma_bf16(acc[i][j], ah[i], bl[j >> 1][j & 1], bl[j >> 1][2 + (j & 1)]);
#pragma unroll
            for (int i = 0; i < 4; i++) {
                uint32_t ra = (uint32_t)(((wm + i * 16 + lrow) * RS + kb + lkc) * 2);
                LDMX4(al[i][0], al[i][1], al[i][2], al[i][3], sAl + ra);
            }
#pragma unroll
            for (int i = 0; i < 4; i++)
#pragma unroll
                for (int j = 0; j < 4; j++)
                    mma_bf16(acc[i][j], al[i], bh[j >> 1][j & 1], bh[j >> 1][2 + (j & 1)]);
        }
    }

    const int er = ln >> 2;
    const int ec = (ln & 3) * 2;
#pragma unroll
    for (int i = 0; i < 4; i++) {
#pragma unroll
        for (int j = 0; j < 4; j++) {
            const int col = n0 + wn + j * 8 + ec;
            const float b0 = __ldg(bias + col), b1 = __ldg(bias + col + 1);
            const int r0 = m0 + wm + i * 16 + er;
            float2 o0 = make_float2(acc[i][j][0] + b0, acc[i][j][1] + b1);
            float2 o1 = make_float2(acc[i][j][2] + b0, acc[i][j][3] + b1);
            *(float2*)(C + (size_t)r0 * N + col) = o0;
            *(float2*)(C + (size_t)(r0 + 8) * N + col) = o1;
        }
    }
}

// ---------------------------------------------------------------------------
// HMMA flash attention.
// FIX vs round 9: AST=72 (144 B/row, multiple of 16 as ldmatrix requires;
// AST=68 -> 136 B rows caused "misaligned address"). 144B stride is also
// bank-conflict-free for ldmatrix row groups. Smem total 45 KB.
// ---------------------------------------------------------------------------
#define AQT 64
#define AKT 64
#define AST 72   // elem stride for 64-wide attn tiles: 144 bytes = 9*16

__global__ __launch_bounds__(128) void attn_mma(const float* __restrict__ qkv,
                                                float* __restrict__ ctx)
{
    __shared__ __nv_bfloat16 KQh[AKT * AST], KQl[AKT * AST]; // Q staging, then K tiles
    __shared__ __half VTh[64 * AST], VTl[64 * AST];          // V^T: [d][key]
    __shared__ __half Psm[4 * 16 * AST];                     // per-warp P [16][64]

    const int t = threadIdx.x, wid = t >> 5, ln = t & 31;
    const int bh = blockIdx.y, b = bh >> 4, h = bh & 15;
    const int q0 = blockIdx.x * AQT;
    const float C1 = 0.125f * 1.44269504f;   // scale * log2(e)

    // stage Q (hi/lo bf16) into the K buffers (overlaid)
    const float* Qg = qkv + ((size_t)(b * Sq + q0)) * 3072 + h * 64;
#pragma unroll
    for (int i = 0; i < 8; i++) {
        int idx = i * 128 + t;
        int row = idx >> 4, c4 = idx & 15;
        float4 v = *(const float4*)(Qg + (size_t)row * 3072 + c4 * 4);
        uint2 hp, lp;
        split4(v, hp, lp);
        *(uint2*)&KQh[row * AST + c4 * 4] = hp;
        *(uint2*)&KQl[row * AST + c4 * 4] = lp;
    }
    __syncthreads();

    const uint32_t sKQh = smem_u32(KQh), sKQl = smem_u32(KQl);
    const uint32_t sVh = smem_u32(VTh), sVl = smem_u32(VTl);
    __half* Pw = Psm + wid * 16 * AST;
    const uint32_t sPw = smem_u32(Pw);

    const int lrow = (ln & 7) + ((ln >> 3) & 1) * 8;
    const int lkc  = (ln >> 4) * 8;
    const int wq   = wid * 16;
    const int er   = ln >> 2;
    const int ec   = (ln & 3) * 2;

    // Q fragments -> registers (then the KQ buffers are free for K tiles)
    uint32_t qh[4][4], ql[4][4];
#pragma unroll
    for (int c = 0; c < 4; c++) {
        uint32_t a = (uint32_t)(((wq + lrow) * AST + c * 16 + lkc) * 2);
        LDMX4(qh[c][0], qh[c][1], qh[c][2], qh[c][3], sKQh + a);
        LDMX4(ql[c][0], ql[c][1], ql[c][2], ql[c][3], sKQl + a);
    }

    float accd[8][4];
#pragma unroll
    for (int j = 0; j < 8; j++)
#pragma unroll
        for (int f = 0; f < 4; f++) accd[j][f] = 0.f;
    float my0 = -1e30f, my1 = -1e30f, l0 = 0.f, l1 = 0.f;

    const float* Kg = qkv + (size_t)(b * Sq) * 3072 + 1024 + h * 64;

    for (int kt = 0; kt < Sq; kt += AKT) {
        __syncthreads();   // all warps done reading previous tiles / Q staging
        // stage K (hi/lo bf16, row-major) and V^T (hi/lo fp16, [d][key])
#pragma unroll
        for (int i = 0; i < 8; i++) {
            int idx = i * 128 + t;
            int row = idx >> 4, c4 = idx & 15;   // row = key index in tile
            const float* kp = Kg + (size_t)(kt + row) * 3072 + c4 * 4;
            float4 kv4 = *(const float4*)kp;
            float4 vv4 = *(const float4*)(kp + 1024);
            uint2 hp, lp;
            split4(kv4, hp, lp);
            *(uint2*)&KQh[row * AST + c4 * 4] = hp;
            *(uint2*)&KQl[row * AST + c4 * 4] = lp;
            const int d0 = c4 * 4;
            float xs0 = vv4.x, xs1 = vv4.y, xs2 = vv4.z, xs3 = vv4.w;
            __half hh;
            hh = __float2half(xs0);
            VTh[(d0 + 0) * AST + row] = hh;
            VTl[(d0 + 0) * AST + row] = __float2half(xs0 - __half2float(hh));
            hh = __float2half(xs1);
            VTh[(d0 + 1) * AST + row] = hh;
            VTl[(d0 + 1) * AST + row] = __float2half(xs1 - __half2float(hh));
            hh = __float2half(xs2);
            VTh[(d0 + 2) * AST + row] = hh;
            VTl[(d0 + 2) * AST + row] = __float2half(xs2 - __half2float(hh));
            hh = __float2half(xs3);
            VTh[(d0 + 3) * AST + row] = hh;
            VTl[(d0 + 3) * AST + row] = __float2half(xs3 - __half2float(hh));
        }
        __syncthreads();

        // S = Q K^T (split bf16, 3-term) -- GEMM-identical pattern
        float s[8][4];
#pragma unroll
        for (int j = 0; j < 8; j++)
#pragma unroll
            for (int f = 0; f < 4; f++) s[j][f] = 0.f;

#pragma unroll
        for (int c = 0; c < 4; c++) {
            uint32_t kh[4][4], kl[4][4];
#pragma unroll
            for (int J = 0; J < 4; J++) {
                uint32_t a = (uint32_t)(((J * 16 + lrow) * AST + c * 16 + lkc) * 2);
                LDMX4(kh[J][0], kh[J][1], kh[J][2], kh[J][3], sKQh + a);
                LDMX4(kl[J][0], kl[J][1], kl[J][2], kl[J][3], sKQl + a);
            }
#pragma unroll
            for (int J = 0; J < 4; J++)
#pragma unroll
                for (int u = 0; u < 2; u++) {
                    int j = 2 * J + u;
                    mma_bf16(s[j], qh[c], kh[J][u], kh[J][2 + u]);
                    mma_bf16(s[j], qh[c], kl[J][u], kl[J][2 + u]);
                    mma_bf16(s[j], ql[c], kh[J][u], kh[J][2 + u]);
                }
        }

        // online softmax (y-units = score*scale*log2e)
        float tm0 = -1e30f, tm1 = -1e30f;
#pragma unroll
        for (int j = 0; j < 8; j++) {
            tm0 = fmaxf(tm0, fmaxf(s[j][0], s[j][1]));
            tm1 = fmaxf(tm1, fmaxf(s[j][2], s[j][3]));
        }
        tm0 *= C1; tm1 *= C1;
        tm0 = fmaxf(tm0, __shfl_xor_sync(0xffffffffu, tm0, 1));
        tm0 = fmaxf(tm0, __shfl_xor_sync(0xffffffffu, tm0, 2));
        tm1 = fmaxf(tm1, __shfl_xor_sync(0xffffffffu, tm1, 1));
        tm1 = fmaxf(tm1, __shfl_xor_sync(0xffffffffu, tm1, 2));
        float mn0 = fmaxf(my0, tm0), mn1 = fmaxf(my1, tm1);
        float corr0 = exp2_fast(my0 - mn0), corr1 = exp2_fast(my1 - mn1);
        my0 = mn0; my1 = mn1;

        float rs0 = 0.f, rs1 = 0.f;
#pragma unroll
        for (int j = 0; j < 8; j++) {
            s[j][0] = exp2_fast(fmaf(s[j][0], C1, -mn0));
            s[j][1] = exp2_fast(fmaf(s[j][1], C1, -mn0));
            s[j][2] = exp2_fast(fmaf(s[j][2], C1, -mn1));
            s[j][3] = exp2_fast(fmaf(s[j][3], C1, -mn1));
            rs0 += s[j][0] + s[j][1];
            rs1 += s[j][2] + s[j][3];
        }
        rs0 += __shfl_xor_sync(0xffffffffu, rs0, 1);
        rs0 += __shfl_xor_sync(0xffffffffu, rs0, 2);
        rs1 += __shfl_xor_sync(0xffffffffu, rs1, 1);
        rs1 += __shfl_xor_sync(0xffffffffu, rs1, 2);
        l0 = l0 * corr0 + rs0;
        l1 = l1 * corr1 + rs1;
#pragma unroll
        for (int j = 0; j < 8; j++) {
            accd[j][0] *= corr0; accd[j][1] *= corr0;
            accd[j][2] *= corr1; accd[j][3] *= corr1;
        }

        // P -> per-warp smem as fp16 at known (row, col) positions
#pragma unroll
        for (int j = 0; j < 8; j++) {
            __half2 p01 = __floats2half2_rn(s[j][0], s[j][1]);
            __half2 p23 = __floats2half2_rn(s[j][2], s[j][3]);
            *(__half2*)&Pw[er * AST + j * 8 + ec] = p01;
            *(__half2*)&Pw[(er + 8) * AST + j * 8 + ec] = p23;
        }
        __syncwarp();

        // ctx += P * V  via GEMM-pattern fragments:
        // A = P [16 q][64 key] (non-trans ldmatrix), B = V^T [64 d][64 key]
#pragma unroll
        for (int tt = 0; tt < 4; tt++) {
            uint32_t pa[4];
            uint32_t pad = sPw + (uint32_t)((lrow * AST + tt * 16 + lkc) * 2);
            LDMX4(pa[0], pa[1], pa[2], pa[3], pad);
#pragma unroll
            for (int Jd = 0; Jd < 4; Jd++) {
                uint32_t vh[4], vl[4];
                uint32_t va = (uint32_t)(((Jd * 16 + lrow) * AST + tt * 16 + lkc) * 2);
                LDMX4(vh[0], vh[1], vh[2], vh[3], sVh + va);
                LDMX4(vl[0], vl[1], vl[2], vl[3], sVl + va);
                mma_f16(accd[2 * Jd + 0], pa, vh[0], vh[2]);
                mma_f16(accd[2 * Jd + 1], pa, vh[1], vh[3]);
                mma_f16(accd[2 * Jd + 0], pa, vl[0], vl[2]);
                mma_f16(accd[2 * Jd + 1], pa, vl[1], vl[3]);
            }
        }
        __syncwarp();
    }

    // epilogue: ctx[b, q, h*64 + d] = acc / l
    const float inv0 = 1.0f / l0, inv1 = 1.0f / l1;
    float* Cb = ctx + (size_t)(b * Sq + q0 + wq) * Eq + h * 64;
#pragma unroll
    for (int j = 0; j < 8; j++) {
        float2 o0 = make_float2(accd[j][0] * inv0, accd[j][1] * inv0);
        float2 o1 = make_float2(accd[j][2] * inv1, accd[j][3] * inv1);
        *(float2*)(Cb + (size_t)er * Eq + 8 * j + ec) = o0;
        *(float2*)(Cb + (size_t)(er + 8) * Eq + 8 * j + ec) = o1;
    }
}

// ---------------------------------------------------------------------------
// Launch
// ---------------------------------------------------------------------------
extern "C" void kernel_launch(void* const* d_in, const int* in_sizes, int n_in,
                              void* d_out, int out_size)
{
    const float* inp   = (const float*)d_in[0];
    const float* qkv_w = (const float*)d_in[1];
    const float* qkv_b = (const float*)d_in[2];
    const float* out_w = (const float*)d_in[3];
    const float* out_b = (const float*)d_in[4];
    float* out = (float*)d_out;

    float* qkv_buf = nullptr;
    float* ctx_buf = nullptr;
    cudaGetSymbolAddress((void**)&qkv_buf, g_qkv);
    cudaGetSymbolAddress((void**)&ctx_buf, g_ctx);

    const int M = Bq * Sq; // 8192

    // 1) QKV projection
    {
        dim3 grid(3 * Eq / BN, M / BM); // (24, 64)
        gemm_mma<<<grid, 256>>>(inp, qkv_w, qkv_b, qkv_buf, M, 3 * Eq, Eq);
    }
    // 2) Attention (HMMA flash)
    {
        dim3 grid(Sq / AQT, Bq * Hq); // (32, 64)
        attn_mma<<<grid, 128>>>(qkv_buf, ctx_buf);
    }
    // 3) Output projection
    {
        dim3 grid(Eq / BN, M / BM); // (8, 64)
        gemm_mma<<<grid, 256>>>(ctx_buf, out_w, out_b, out, M, Eq, Eq);
    }
}

// round 14
// speedup vs baseline: 3.2791x; 1.3546x over previous
#include <cuda_runtime.h>
#include <cuda_bf16.h>
#include <cuda_fp16.h>
#include <cstdint>

#define Bq 4
#define Sq 2048
#define Eq 1024
#define Hq 16

// Scratch (allocation-free rule)
__device__ float g_qkv[(size_t)Bq * Sq * 3 * Eq]; // [b,s, c*1024 + h*64 + d]
__device__ float g_ctx[(size_t)Bq * Sq * Eq];
__device__ __nv_bfloat16 g_khi[(size_t)Bq * Hq * Sq * 64]; // [b,h,s,d]
__device__ __nv_bfloat16 g_klo[(size_t)Bq * Hq * Sq * 64];
__device__ __half g_vt[(size_t)Bq * Hq * 64 * Sq];         // [b,h,d,s]

// ---------------------------------------------------------------------------
// mma.sync helpers
// ---------------------------------------------------------------------------
__device__ __forceinline__ uint32_t smem_u32(const void* p) {
    uint32_t a;
    asm("{ .reg .u64 t; cvta.to.shared.u64 t, %1; cvt.u32.u64 %0, t; }"
        : "=r"(a) : "l"(p));
    return a;
}

#define LDMX4(r0, r1, r2, r3, addr)                                         \
    asm volatile("ldmatrix.sync.aligned.m8n8.x4.shared.b16 {%0,%1,%2,%3}, [%4];" \
                 : "=r"(r0), "=r"(r1), "=r"(r2), "=r"(r3) : "r"(addr))

__device__ __forceinline__ void mma_bf16(float* c, const uint32_t* a,
                                         uint32_t b0, uint32_t b1) {
    asm volatile("mma.sync.aligned.m16n8k16.row.col.f32.bf16.bf16.f32 "
                 "{%0,%1,%2,%3}, {%4,%5,%6,%7}, {%8,%9}, {%0,%1,%2,%3};"
                 : "+f"(c[0]), "+f"(c[1]), "+f"(c[2]), "+f"(c[3])
                 : "r"(a[0]), "r"(a[1]), "r"(a[2]), "r"(a[3]), "r"(b0), "r"(b1));
}

__device__ __forceinline__ void mma_f16(float* c, const uint32_t* a,
                                        uint32_t b0, uint32_t b1) {
    asm volatile("mma.sync.aligned.m16n8k16.row.col.f32.f16.f16.f32 "
                 "{%0,%1,%2,%3}, {%4,%5,%6,%7}, {%8,%9}, {%0,%1,%2,%3};"
                 : "+f"(c[0]), "+f"(c[1]), "+f"(c[2]), "+f"(c[3])
                 : "r"(a[0]), "r"(a[1]), "r"(a[2]), "r"(a[3]), "r"(b0), "r"(b1));
}

// split fp32 -> (hi, lo) bf16 packed
__device__ __forceinline__ void split4(float4 v, uint2& hp, uint2& lp) {
    __nv_bfloat16 h0 = __float2bfloat16(v.x), h1 = __float2bfloat16(v.y);
    __nv_bfloat16 h2 = __float2bfloat16(v.z), h3 = __float2bfloat16(v.w);
    __nv_bfloat16 l0 = __float2bfloat16(v.x - __bfloat162float(h0));
    __nv_bfloat16 l1 = __float2bfloat16(v.y - __bfloat162float(h1));
    __nv_bfloat16 l2 = __float2bfloat16(v.z - __bfloat162float(h2));
    __nv_bfloat16 l3 = __float2bfloat16(v.w - __bfloat162float(h3));
    hp.x = (uint32_t)__bfloat16_as_ushort(h0) | ((uint32_t)__bfloat16_as_ushort(h1) << 16);
    hp.y = (uint32_t)__bfloat16_as_ushort(h2) | ((uint32_t)__bfloat16_as_ushort(h3) << 16);
    lp.x = (uint32_t)__bfloat16_as_ushort(l0) | ((uint32_t)__bfloat16_as_ushort(l1) << 16);
    lp.y = (uint32_t)__bfloat16_as_ushort(l2) | ((uint32_t)__bfloat16_as_ushort(l3) << 16);
}

// fast exp2 on FMA pipe (arg <= 0 expected), rel err ~2e-6
__device__ __forceinline__ float exp2_fast(float y) {
    y = fmaxf(y, -60.0f);
    int e = __float2int_rn(y);
    float f = y - __int2float_rn(e);
    float p = 1.3333558e-3f;
    p = fmaf(p, f, 9.6181291e-3f);
    p = fmaf(p, f, 5.5504109e-2f);
    p = fmaf(p, f, 2.4022651e-1f);
    p = fmaf(p, f, 6.9314718e-1f);
    p = fmaf(p, f, 1.0f);
    return __int_as_float((e + 127) << 23) * p;
}

// ---------------------------------------------------------------------------
// Split-bf16 HMMA GEMM: C = A*B^T + bias (proven, unchanged)
// ---------------------------------------------------------------------------
#define BM 128
#define BN 128
#define BKc 32
#define RS 40

__global__ __launch_bounds__(256, 1) void gemm_mma(const float* __restrict__ A,
                                                   const float* __restrict__ B,
                                                   const float* __restrict__ bias,
                                                   float* __restrict__ C,
                                                   int M, int N, int K)
{
    __shared__ __nv_bfloat16 Ah[BM * RS], Al[BM * RS];
    __shared__ __nv_bfloat16 Bh[BN * RS], Bl[BN * RS];

    const int t   = threadIdx.x;
    const int wid = t >> 5;
    const int ln  = t & 31;
    const int m0  = blockIdx.y * BM;
    const int n0  = blockIdx.x * BN;
    const int wm  = (wid >> 2) * 64;
    const int wn  = (wid & 3) * 32;

    const float* Abase = A + (size_t)m0 * K;
    const float* Bbase = B + (size_t)n0 * K;

    float acc[4][4][4];
#pragma unroll
    for (int i = 0; i < 4; i++)
#pragma unroll
        for (int j = 0; j < 4; j++)
#pragma unroll
            for (int f = 0; f < 4; f++) acc[i][j][f] = 0.f;

    const uint32_t sAh = smem_u32(Ah), sAl = smem_u32(Al);
    const uint32_t sBh = smem_u32(Bh), sBl = smem_u32(Bl);
    const int lrow = (ln & 7) + ((ln >> 3) & 1) * 8;
    const int lkc  = (ln >> 4) * 8;

    const int NC = K / BKc;
    float4 av[4], bv[4];

#pragma unroll
    for (int i = 0; i < 4; i++) {
        int idx = i * 256 + t;
        int row = idx >> 3, c4 = idx & 7;
        av[i] = *(const float4*)(Abase + (size_t)row * K + c4 * 4);
        bv[i] = *(const float4*)(Bbase + (size_t)row * K + c4 * 4);
    }

    for (int kc = 0; kc < NC; kc++) {
        __syncthreads();
#pragma unroll
        for (int i = 0; i < 4; i++) {
            int idx = i * 256 + t;
            int row = idx >> 3, c4 = idx & 7;
            uint2 hp, lp;
            split4(av[i], hp, lp);
            *(uint2*)&Ah[row * RS + c4 * 4] = hp;
            *(uint2*)&Al[row * RS + c4 * 4] = lp;
            split4(bv[i], hp, lp);
            *(uint2*)&Bh[row * RS + c4 * 4] = hp;
            *(uint2*)&Bl[row * RS + c4 * 4] = lp;
        }
        __syncthreads();

        if (kc + 1 < NC) {
            const int k0n = (kc + 1) * BKc;
#pragma unroll
            for (int i = 0; i < 4; i++) {
                int idx = i * 256 + t;
                int row = idx >> 3, c4 = idx & 7;
                av[i] = *(const float4*)(Abase + (size_t)row * K + k0n + c4 * 4);
                bv[i] = *(const float4*)(Bbase + (size_t)row * K + k0n + c4 * 4);
            }
        }

#pragma unroll
        for (int ks = 0; ks < 2; ks++) {
            const int kb = ks * 16;
            uint32_t ah[4][4], al[4][4], bh[2][4], bl[2][4];
#pragma unroll
            for (int i = 0; i < 4; i++) {
                uint32_t ra = (uint32_t)(((wm + i * 16 + lrow) * RS + kb + lkc) * 2);
                LDMX4(ah[i][0], ah[i][1], ah[i][2], ah[i][3], sAh + ra);
            }
#pragma unroll
            for (int j = 0; j < 2; j++) {
                uint32_t rb = (uint32_t)(((wn + j * 16 + lrow) * RS + kb + lkc) * 2);
                LDMX4(bh[j][0], bh[j][1], bh[j][2], bh[j][3], sBh + rb);
            }
#pragma unroll
            for (int i = 0; i < 4; i++)
#pragma unroll
                for (int j = 0; j < 4; j++)
                    mma_bf16(acc[i][j], ah[i], bh[j >> 1][j & 1], bh[j >> 1][2 + (j & 1)]);
#pragma unroll
            for (int j = 0; j < 2; j++) {
                uint32_t rb = (uint32_t)(((wn + j * 16 + lrow) * RS + kb + lkc) * 2);
                LDMX4(bl[j][0], bl[j][1], bl[j][2], bl[j][3], sBl + rb);
            }
#pragma unroll
            for (int i = 0; i < 4; i++)
#pragma unroll
                for (int j = 0; j < 4; j++)
                    mma_bf16(acc[i][j], ah[i], bl[j >> 1][j & 1], bl[j >> 1][2 + (j & 1)]);
#pragma unroll
            for (int i = 0; i < 4; i++) {
                uint32_t ra = (uint32_t)(((wm + i * 16 + lrow) * RS + kb + lkc) * 2);
                LDMX4(al[i][0], al[i][1], al[i][2], al[i][3], sAl + ra);
            }
#pragma unroll
            for (int i = 0; i < 4; i++)
#pragma unroll
                for (int j = 0; j < 4; j++)
                    mma_bf16(acc[i][j], al[i], bh[j >> 1][j & 1], bh[j >> 1][2 + (j & 1)]);
        }
    }

    const int er = ln >> 2;
    const int ec = (ln & 3) * 2;
#pragma unroll
    for (int i = 0; i < 4; i++) {
#pragma unroll
        for (int j = 0; j < 4; j++) {
            const int col = n0 + wn + j * 8 + ec;
            const float b0 = __ldg(bias + col), b1 = __ldg(bias + col + 1);
            const int r0 = m0 + wm + i * 16 + er;
            float2 o0 = make_float2(acc[i][j][0] + b0, acc[i][j][1] + b1);
            float2 o1 = make_float2(acc[i][j][2] + b0, acc[i][j][3] + b1);
            *(float2*)(C + (size_t)r0 * N + col) = o0;
            *(float2*)(C + (size_t)(r0 + 8) * N + col) = o1;
        }
    }
}

// ---------------------------------------------------------------------------
// K conversion: qkv fp32 -> Khi/Klo bf16 [b,h,s,d]. One thread per float4.
// ---------------------------------------------------------------------------
__global__ __launch_bounds__(256) void convert_k(const float* __restrict__ qkv,
                                                 __nv_bfloat16* __restrict__ khi,
                                                 __nv_bfloat16* __restrict__ klo)
{
    size_t i = (size_t)blockIdx.x * 256 + threadIdx.x;  // over [b][s][h][d4]
    int d4 = i & 15;
    int s  = (i >> 4) & 2047;
    int h  = (i >> 15) & 15;
    int b  = (int)(i >> 19);
    float4 v = *(const float4*)(qkv + ((size_t)(b * Sq + s)) * 3072 + 1024 + h * 64 + d4 * 4);
    uint2 hp, lp;
    split4(v, hp, lp);
    size_t o = (((size_t)(b * Hq + h) * Sq + s) * 64 + d4 * 4);
    *(uint2*)(khi + o) = hp;
    *(uint2*)(klo + o) = lp;
}

// ---------------------------------------------------------------------------
// V transpose: qkv fp32 [b,s,h,d] -> Vt fp16 [b,h,d,s]. Tiled via smem.
// grid = (S/64, B*H), 128 threads.
// ---------------------------------------------------------------------------
__global__ __launch_bounds__(128) void convert_vt(const float* __restrict__ qkv,
                                                  __half* __restrict__ vt)
{
    __shared__ __half tile[64][72];
    const int bh = blockIdx.y, b = bh >> 4, h = bh & 15;
    const int s0 = blockIdx.x * 64;
    const int t = threadIdx.x;

#pragma unroll
    for (int i = 0; i < 8; i++) {
        int idx = i * 128 + t;
        int srow = idx >> 4, d4 = idx & 15;
        float4 v = *(const float4*)(qkv + ((size_t)(b * Sq + s0 + srow)) * 3072 + 2048 + h * 64 + d4 * 4);
        tile[d4 * 4 + 0][srow] = __float2half(v.x);
        tile[d4 * 4 + 1][srow] = __float2half(v.y);
        tile[d4 * 4 + 2][srow] = __float2half(v.z);
        tile[d4 * 4 + 3][srow] = __float2half(v.w);
    }
    __syncthreads();

#pragma unroll
    for (int i = 0; i < 4; i++) {
        int idx = i * 128 + t;
        int d = idx >> 3, sg = (idx & 7) * 8;
        uint4 val = *(uint4*)&tile[d][sg];
        *(uint4*)(vt + ((size_t)bh * 64 + d) * Sq + s0 + sg) = val;
    }
}

// ---------------------------------------------------------------------------
// HMMA flash attention. K/V pre-converted in global memory:
//   Khi/Klo bf16 [b,h,s,d]; Vt fp16 [b,h,d,s] (single-term fp16 V).
// Staging is pure uint4 copies. S = 3-term split bf16; PV = fp16 (P via smem).
// ---------------------------------------------------------------------------
#define AQT 64
#define AKT 64
#define AST 72   // 144 B rows (16B multiple for ldmatrix)

__global__ __launch_bounds__(128) void attn_mma(const float* __restrict__ qkv,
                                                const __nv_bfloat16* __restrict__ khig,
                                                const __nv_bfloat16* __restrict__ klog,
                                                const __half* __restrict__ vtg,
                                                float* __restrict__ ctx)
{
    __shared__ __nv_bfloat16 KQh[AKT * AST], KQl[AKT * AST]; // Q staging, then K tiles
    __shared__ __half VT[64 * AST];                          // V^T tile [d][key]
    __shared__ __half Psm[4 * 16 * AST];                     // per-warp P [16][64]

    const int t = threadIdx.x, wid = t >> 5, ln = t & 31;
    const int bh = blockIdx.y, b = bh >> 4, h = bh & 15;
    const int q0 = blockIdx.x * AQT;
    const float C1 = 0.125f * 1.44269504f;

    // stage Q (hi/lo bf16) into the K buffers (overlaid)
    const float* Qg = qkv + ((size_t)(b * Sq + q0)) * 3072 + h * 64;
#pragma unroll
    for (int i = 0; i < 8; i++) {
        int idx = i * 128 + t;
        int row = idx >> 4, c4 = idx & 15;
        float4 v = *(const float4*)(Qg + (size_t)row * 3072 + c4 * 4);
        uint2 hp, lp;
        split4(v, hp, lp);
        *(uint2*)&KQh[row * AST + c4 * 4] = hp;
        *(uint2*)&KQl[row * AST + c4 * 4] = lp;
    }
    __syncthreads();

    const uint32_t sKQh = smem_u32(KQh), sKQl = smem_u32(KQl);
    const uint32_t sVT = smem_u32(VT);
    __half* Pw = Psm + wid * 16 * AST;
    const uint32_t sPw = smem_u32(Pw);

    const int lrow = (ln & 7) + ((ln >> 3) & 1) * 8;
    const int lkc  = (ln >> 4) * 8;
    const int wq   = wid * 16;
    const int er   = ln >> 2;
    const int ec   = (ln & 3) * 2;

    uint32_t qh[4][4], ql[4][4];
#pragma unroll
    for (int c = 0; c < 4; c++) {
        uint32_t a = (uint32_t)(((wq + lrow) * AST + c * 16 + lkc) * 2);
        LDMX4(qh[c][0], qh[c][1], qh[c][2], qh[c][3], sKQh + a);
        LDMX4(ql[c][0], ql[c][1], ql[c][2], ql[c][3], sKQl + a);
    }

    float accd[8][4];
#pragma unroll
    for (int j = 0; j < 8; j++)
#pragma unroll
        for (int f = 0; f < 4; f++) accd[j][f] = 0.f;
    float my0 = -1e30f, my1 = -1e30f, l0 = 0.f, l1 = 0.f;

    const __nv_bfloat16* Khb = khig + (size_t)bh * Sq * 64;
    const __nv_bfloat16* Klb = klog + (size_t)bh * Sq * 64;
    const __half* Vtb = vtg + (size_t)bh * 64 * Sq;

    for (int kt = 0; kt < Sq; kt += AKT) {
        __syncthreads();
        // stage K hi/lo + V^T tile: pure uint4 copies (no conversion)
#pragma unroll
        for (int i = 0; i < 4; i++) {
            int idx = i * 128 + t;
            int row = idx >> 3, c8 = (idx & 7) * 8;
            *(uint4*)&KQh[row * AST + c8] = *(const uint4*)(Khb + (size_t)(kt + row) * 64 + c8);
            *(uint4*)&KQl[row * AST + c8] = *(const uint4*)(Klb + (size_t)(kt + row) * 64 + c8);
            *(uint4*)&VT[row * AST + c8]  = *(const uint4*)(Vtb + (size_t)row * Sq + kt + c8);
        }
        __syncthreads();

        // S = Q K^T (split bf16, 3-term)
        float s[8][4];
#pragma unroll
        for (int j = 0; j < 8; j++)
#pragma unroll
            for (int f = 0; f < 4; f++) s[j][f] = 0.f;

#pragma unroll
        for (int c = 0; c < 4; c++) {
            uint32_t kh[4][4], kl[4][4];
#pragma unroll
            for (int J = 0; J < 4; J++) {
                uint32_t a = (uint32_t)(((J * 16 + lrow) * AST + c * 16 + lkc) * 2);
                LDMX4(kh[J][0], kh[J][1], kh[J][2], kh[J][3], sKQh + a);
                LDMX4(kl[J][0], kl[J][1], kl[J][2], kl[J][3], sKQl + a);
            }
#pragma unroll
            for (int J = 0; J < 4; J++)
#pragma unroll
                for (int u = 0; u < 2; u++) {
                    int j = 2 * J + u;
                    mma_bf16(s[j], qh[c], kh[J][u], kh[J][2 + u]);
                    mma_bf16(s[j], qh[c], kl[J][u], kl[J][2 + u]);
                    mma_bf16(s[j], ql[c], kh[J][u], kh[J][2 + u]);
                }
        }

        // online softmax
        float tm0 = -1e30f, tm1 = -1e30f;
#pragma unroll
        for (int j = 0; j < 8; j++) {
            tm0 = fmaxf(tm0, fmaxf(s[j][0], s[j][1]));
            tm1 = fmaxf(tm1, fmaxf(s[j][2], s[j][3]));
        }
        tm0 *= C1; tm1 *= C1;
        tm0 = fmaxf(tm0, __shfl_xor_sync(0xffffffffu, tm0, 1));
        tm0 = fmaxf(tm0, __shfl_xor_sync(0xffffffffu, tm0, 2));
        tm1 = fmaxf(tm1, __shfl_xor_sync(0xffffffffu, tm1, 1));
        tm1 = fmaxf(tm1, __shfl_xor_sync(0xffffffffu, tm1, 2));
        float mn0 = fmaxf(my0, tm0), mn1 = fmaxf(my1, tm1);
        float corr0 = exp2_fast(my0 - mn0), corr1 = exp2_fast(my1 - mn1);
        my0 = mn0; my1 = mn1;

        float rs0 = 0.f, rs1 = 0.f;
#pragma unroll
        for (int j = 0; j < 8; j++) {
            s[j][0] = exp2_fast(fmaf(s[j][0], C1, -mn0));
            s[j][1] = exp2_fast(fmaf(s[j][1], C1, -mn0));
            s[j][2] = exp2_fast(fmaf(s[j][2], C1, -mn1));
            s[j][3] = exp2_fast(fmaf(s[j][3], C1, -mn1));
            rs0 += s[j][0] + s[j][1];
            rs1 += s[j][2] + s[j][3];
        }
        rs0 += __shfl_xor_sync(0xffffffffu, rs0, 1);
        rs0 += __shfl_xor_sync(0xffffffffu, rs0, 2);
        rs1 += __shfl_xor_sync(0xffffffffu, rs1, 1);
        rs1 += __shfl_xor_sync(0xffffffffu, rs1, 2);
        l0 = l0 * corr0 + rs0;
        l1 = l1 * corr1 + rs1;
#pragma unroll
        for (int j = 0; j < 8; j++) {
            accd[j][0] *= corr0; accd[j][1] *= corr0;
            accd[j][2] *= corr1; accd[j][3] *= corr1;
        }

        // P -> per-warp smem as fp16
#pragma unroll
        for (int j = 0; j < 8; j++) {
            __half2 p01 = __floats2half2_rn(s[j][0], s[j][1]);
            __half2 p23 = __floats2half2_rn(s[j][2], s[j][3]);
            *(__half2*)&Pw[er * AST + j * 8 + ec] = p01;
            *(__half2*)&Pw[(er + 8) * AST + j * 8 + ec] = p23;
        }
        __syncwarp();

        // ctx += P * V  (A = P via ldmatrix, B = V^T [d][key], single fp16)
#pragma unroll
        for (int tt = 0; tt < 4; tt++) {
            uint32_t pa[4];
            uint32_t pad = sPw + (uint32_t)((lrow * AST + tt * 16 + lkc) * 2);
            LDMX4(pa[0], pa[1], pa[2], pa[3], pad);
#pragma unroll
            for (int Jd = 0; Jd < 4; Jd++) {
                uint32_t vh[4];
                uint32_t va = (uint32_t)(((Jd * 16 + lrow) * AST + tt * 16 + lkc) * 2);
                LDMX4(vh[0], vh[1], vh[2], vh[3], sVT + va);
                mma_f16(accd[2 * Jd + 0], pa, vh[0], vh[2]);
                mma_f16(accd[2 * Jd + 1], pa, vh[1], vh[3]);
            }
        }
        __syncwarp();
    }

    // epilogue
    const float inv0 = 1.0f / l0, inv1 = 1.0f / l1;
    float* Cb = ctx + (size_t)(b * Sq + q0 + wq) * Eq + h * 64;
#pragma unroll
    for (int j = 0; j < 8; j++) {
        float2 o0 = make_float2(accd[j][0] * inv0, accd[j][1] * inv0);
        float2 o1 = make_float2(accd[j][2] * inv1, accd[j][3] * inv1);
        *(float2*)(Cb + (size_t)er * Eq + 8 * j + ec) = o0;
        *(float2*)(Cb + (size_t)(er + 8) * Eq + 8 * j + ec) = o1;
    }
}

// ---------------------------------------------------------------------------
// Launch
// ---------------------------------------------------------------------------
extern "C" void kernel_launch(void* const* d_in, const int* in_sizes, int n_in,
                              void* d_out, int out_size)
{
    const float* inp   = (const float*)d_in[0];
    const float* qkv_w = (const float*)d_in[1];
    const float* qkv_b = (const float*)d_in[2];
    const float* out_w = (const float*)d_in[3];
    const float* out_b = (const float*)d_in[4];
    float* out = (float*)d_out;

    float* qkv_buf = nullptr;
    float* ctx_buf = nullptr;
    __nv_bfloat16* khi = nullptr;
    __nv_bfloat16* klo = nullptr;
    __half* vt = nullptr;
    cudaGetSymbolAddress((void**)&qkv_buf, g_qkv);
    cudaGetSymbolAddress((void**)&ctx_buf, g_ctx);
    cudaGetSymbolAddress((void**)&khi, g_khi);
    cudaGetSymbolAddress((void**)&klo, g_klo);
    cudaGetSymbolAddress((void**)&vt, g_vt);

    const int M = Bq * Sq; // 8192

    // 1) QKV projection
    {
        dim3 grid(3 * Eq / BN, M / BM); // (24, 64)
        gemm_mma<<<grid, 256>>>(inp, qkv_w, qkv_b, qkv_buf, M, 3 * Eq, Eq);
    }
    // 2) K split + V transpose conversion
    {
        convert_k<<<(Bq * Hq * Sq * 16) / 256, 256>>>(qkv_buf, khi, klo);
        dim3 gv(Sq / 64, Bq * Hq);
        convert_vt<<<gv, 128>>>(qkv_buf, vt);
    }
    // 3) Attention (HMMA flash, pre-converted K/V)
    {
        dim3 grid(Sq / AQT, Bq * Hq); // (32, 64)
        attn_mma<<<grid, 128>>>(qkv_buf, khi, klo, vt, ctx_buf);
    }
    // 4) Output projection
    {
        dim3 grid(Eq / BN, M / BM); // (8, 64)
        gemm_mma<<<grid, 256>>>(ctx_buf, out_w, out_b, out, M, Eq, Eq);
    }
}

// round 15
// speedup vs baseline: 3.4762x; 1.0601x over previous
#include <cuda_runtime.h>
#include <cuda_bf16.h>
#include <cuda_fp16.h>
#include <cstdint>

#define Bq 4
#define Sq 2048
#define Eq 1024
#define Hq 16

// Scratch (allocation-free rule)
__device__ float g_qkv[(size_t)Bq * Sq * 3 * Eq]; // [b,s, c*1024 + h*64 + d]
__device__ float g_ctx[(size_t)Bq * Sq * Eq];
__device__ __nv_bfloat16 g_khi[(size_t)Bq * Hq * Sq * 64]; // [b,h,s,d]
__device__ __nv_bfloat16 g_klo[(size_t)Bq * Hq * Sq * 64];
__device__ __half g_vt[(size_t)Bq * Hq * 64 * Sq];         // [b,h,d,s]
// pre-split operands for the GEMMs
__device__ __nv_bfloat16 g_ahi[(size_t)Bq * Sq * Eq], g_alo[(size_t)Bq * Sq * Eq];
__device__ __nv_bfloat16 g_wqh[(size_t)3 * Eq * Eq], g_wql[(size_t)3 * Eq * Eq];
__device__ __nv_bfloat16 g_woh[(size_t)Eq * Eq],     g_wol[(size_t)Eq * Eq];

// ---------------------------------------------------------------------------
// helpers
// ---------------------------------------------------------------------------
__device__ __forceinline__ uint32_t smem_u32(const void* p) {
    uint32_t a;
    asm("{ .reg .u64 t; cvta.to.shared.u64 t, %1; cvt.u32.u64 %0, t; }"
        : "=r"(a) : "l"(p));
    return a;
}

#define LDMX4(r0, r1, r2, r3, addr)                                         \
    asm volatile("ldmatrix.sync.aligned.m8n8.x4.shared.b16 {%0,%1,%2,%3}, [%4];" \
                 : "=r"(r0), "=r"(r1), "=r"(r2), "=r"(r3) : "r"(addr))

#define CP_ASYNC16(saddr, gptr) \
    asm volatile("cp.async.cg.shared.global [%0], [%1], 16;" :: "r"(saddr), "l"(gptr))
#define CP_COMMIT() asm volatile("cp.async.commit_group;" ::: "memory")
#define CP_WAIT0() asm volatile("cp.async.wait_group 0;" ::: "memory")
#define CP_WAIT1() asm volatile("cp.async.wait_group 1;" ::: "memory")

__device__ __forceinline__ void mma_bf16(float* c, const uint32_t* a,
                                         uint32_t b0, uint32_t b1) {
    asm volatile("mma.sync.aligned.m16n8k16.row.col.f32.bf16.bf16.f32 "
                 "{%0,%1,%2,%3}, {%4,%5,%6,%7}, {%8,%9}, {%0,%1,%2,%3};"
                 : "+f"(c[0]), "+f"(c[1]), "+f"(c[2]), "+f"(c[3])
                 : "r"(a[0]), "r"(a[1]), "r"(a[2]), "r"(a[3]), "r"(b0), "r"(b1));
}

__device__ __forceinline__ void mma_f16(float* c, const uint32_t* a,
                                        uint32_t b0, uint32_t b1) {
    asm volatile("mma.sync.aligned.m16n8k16.row.col.f32.f16.f16.f32 "
                 "{%0,%1,%2,%3}, {%4,%5,%6,%7}, {%8,%9}, {%0,%1,%2,%3};"
                 : "+f"(c[0]), "+f"(c[1]), "+f"(c[2]), "+f"(c[3])
                 : "r"(a[0]), "r"(a[1]), "r"(a[2]), "r"(a[3]), "r"(b0), "r"(b1));
}

// split fp32 -> (hi, lo) bf16 packed
__device__ __forceinline__ void split4(float4 v, uint2& hp, uint2& lp) {
    __nv_bfloat16 h0 = __float2bfloat16(v.x), h1 = __float2bfloat16(v.y);
    __nv_bfloat16 h2 = __float2bfloat16(v.z), h3 = __float2bfloat16(v.w);
    __nv_bfloat16 l0 = __float2bfloat16(v.x - __bfloat162float(h0));
    __nv_bfloat16 l1 = __float2bfloat16(v.y - __bfloat162float(h1));
    __nv_bfloat16 l2 = __float2bfloat16(v.z - __bfloat162float(h2));
    __nv_bfloat16 l3 = __float2bfloat16(v.w - __bfloat162float(h3));
    hp.x = (uint32_t)__bfloat16_as_ushort(h0) | ((uint32_t)__bfloat16_as_ushort(h1) << 16);
    hp.y = (uint32_t)__bfloat16_as_ushort(h2) | ((uint32_t)__bfloat16_as_ushort(h3) << 16);
    lp.x = (uint32_t)__bfloat16_as_ushort(l0) | ((uint32_t)__bfloat16_as_ushort(l1) << 16);
    lp.y = (uint32_t)__bfloat16_as_ushort(l2) | ((uint32_t)__bfloat16_as_ushort(l3) << 16);
}

// fast exp2 on FMA pipe (arg <= 0 expected), rel err ~2e-6
__device__ __forceinline__ float exp2_fast(float y) {
    y = fmaxf(y, -60.0f);
    int e = __float2int_rn(y);
    float f = y - __int2float_rn(e);
    float p = 1.3333558e-3f;
    p = fmaf(p, f, 9.6181291e-3f);
    p = fmaf(p, f, 5.5504109e-2f);
    p = fmaf(p, f, 2.4022651e-1f);
    p = fmaf(p, f, 6.9314718e-1f);
    p = fmaf(p, f, 1.0f);
    return __int_as_float((e + 127) << 23) * p;
}

// ---------------------------------------------------------------------------
// Generic fp32 -> hi/lo bf16 split (one thread per float4)
// ---------------------------------------------------------------------------
__global__ __launch_bounds__(256) void convert_split(const float* __restrict__ in,
                                                     __nv_bfloat16* __restrict__ hi,
                                                     __nv_bfloat16* __restrict__ lo)
{
    size_t i = (size_t)blockIdx.x * 256 + threadIdx.x;
    float4 v = ((const float4*)in)[i];
    uint2 hp, lp;
    split4(v, hp, lp);
    ((uint2*)hi)[i] = hp;
    ((uint2*)lo)[i] = lp;
}

// ---------------------------------------------------------------------------
// Pre-split bf16 HMMA GEMM with cp.async double buffering:
//   C[M,N] = A[M,K]*B[N,K]^T + bias[N], A/B given as hi/lo bf16 pairs.
// Tile 128x128, K-chunk 32, 8 warps (2x4), warp tile 64x32. 3-term emulation.
// ---------------------------------------------------------------------------
#define BM 128
#define BN 128
#define BKc 32
#define RS 40
#define GTIL (128 * RS)          // elems per array per stage
#define GTILB (GTIL * 2)         // bytes
#define GSMEM (2 * 4 * GTILB)    // 81920 B dynamic smem

__global__ __launch_bounds__(256) void gemm_bf16(
    const __nv_bfloat16* __restrict__ Ahi, const __nv_bfloat16* __restrict__ Alo,
    const __nv_bfloat16* __restrict__ Bhi, const __nv_bfloat16* __restrict__ Blo,
    const float* __restrict__ bias, float* __restrict__ C,
    int M, int N, int K)
{
    extern __shared__ __align__(16) char dynsm[];
    const uint32_t sb = smem_u32(dynsm);

    const int t   = threadIdx.x;
    const int wid = t >> 5;
    const int ln  = t & 31;
    const int m0  = blockIdx.y * BM;
    const int n0  = blockIdx.x * BN;
    const int wm  = (wid >> 2) * 64;
    const int wn  = (wid & 3) * 32;

    const __nv_bfloat16* Ah_g = Ahi + (size_t)m0 * K;
    const __nv_bfloat16* Al_g = Alo + (size_t)m0 * K;
    const __nv_bfloat16* Bh_g = Bhi + (size_t)n0 * K;
    const __nv_bfloat16* Bl_g = Blo + (size_t)n0 * K;

    // per-thread staging coords: 512 slots of 8 elems per array; 2 per thread
    const int r0s = (t * 2) >> 2, c0s = ((t * 2) & 3) * 8;
    const int r1s = (t * 2 + 1) >> 2, c1s = ((t * 2 + 1) & 3) * 8;

    float acc[4][4][4];
#pragma unroll
    for (int i = 0; i < 4; i++)
#pragma unroll
        for (int j = 0; j < 4; j++)
#pragma unroll
            for (int f = 0; f < 4; f++) acc[i][j][f] = 0.f;

    const int lrow = (ln & 7) + ((ln >> 3) & 1) * 8;
    const int lkc  = (ln >> 4) * 8;
    const int NC = K / BKc;

    // stage(kc, buf): 8 cp.async per thread
    auto stage = [&](int kc, int buf) {
        const int k0 = kc * BKc;
        const uint32_t sbB = sb + buf * 4 * GTILB;
        {
            size_t g0 = (size_t)r0s * K + k0 + c0s;
            size_t g1 = (size_t)r1s * K + k0 + c1s;
            uint32_t o0 = (uint32_t)((r0s * RS + c0s) * 2);
            uint32_t o1 = (uint32_t)((r1s * RS + c1s) * 2);
            CP_ASYNC16(sbB + 0 * GTILB + o0, Ah_g + g0);
            CP_ASYNC16(sbB + 0 * GTILB + o1, Ah_g + g1);
            CP_ASYNC16(sbB + 1 * GTILB + o0, Al_g + g0);
            CP_ASYNC16(sbB + 1 * GTILB + o1, Al_g + g1);
            CP_ASYNC16(sbB + 2 * GTILB + o0, Bh_g + g0);
            CP_ASYNC16(sbB + 2 * GTILB + o1, Bh_g + g1);
            CP_ASYNC16(sbB + 3 * GTILB + o0, Bl_g + g0);
            CP_ASYNC16(sbB + 3 * GTILB + o1, Bl_g + g1);
        }
    };

    stage(0, 0);
    CP_COMMIT();

    for (int kc = 0; kc < NC; kc++) {
        if (kc + 1 < NC) {
            stage(kc + 1, (kc + 1) & 1);
            CP_COMMIT();
            CP_WAIT1();
        } else {
            CP_WAIT0();
        }
        __syncthreads();

        const uint32_t base = sb + (kc & 1) * 4 * GTILB;
        const uint32_t bAh = base + 0 * GTILB;
        const uint32_t bAl = base + 1 * GTILB;
        const uint32_t bBh = base + 2 * GTILB;
        const uint32_t bBl = base + 3 * GTILB;

#pragma unroll
        for (int ks = 0; ks < 2; ks++) {
            const int kb = ks * 16;
            uint32_t ah[4][4], al[4][4], bh[2][4], bl[2][4];
#pragma unroll
            for (int i = 0; i < 4; i++) {
                uint32_t ra = (uint32_t)(((wm + i * 16 + lrow) * RS + kb + lkc) * 2);
                LDMX4(ah[i][0], ah[i][1], ah[i][2], ah[i][3], bAh + ra);
            }
#pragma unroll
            for (int j = 0; j < 2; j++) {
                uint32_t rb = (uint32_t)(((wn + j * 16 + lrow) * RS + kb + lkc) * 2);
                LDMX4(bh[j][0], bh[j][1], bh[j][2], bh[j][3], bBh + rb);
            }
#pragma unroll
            for (int i = 0; i < 4; i++)
#pragma unroll
                for (int j = 0; j < 4; j++)
                    mma_bf16(acc[i][j], ah[i], bh[j >> 1][j & 1], bh[j >> 1][2 + (j & 1)]);
#pragma unroll
            for (int j = 0; j < 2; j++) {
                uint32_t rb = (uint32_t)(((wn + j * 16 + lrow) * RS + kb + lkc) * 2);
                LDMX4(bl[j][0], bl[j][1], bl[j][2], bl[j][3], bBl + rb);
            }
#pragma unroll
            for (int i = 0; i < 4; i++)
#pragma unroll
                for (int j = 0; j < 4; j++)
                    mma_bf16(acc[i][j], ah[i], bl[j >> 1][j & 1], bl[j >> 1][2 + (j & 1)]);
#pragma unroll
            for (int i = 0; i < 4; i++) {
                uint32_t ra = (uint32_t)(((wm + i * 16 + lrow) * RS + kb + lkc) * 2);
                LDMX4(al[i][0], al[i][1], al[i][2], al[i][3], bAl + ra);
            }
#pragma unroll
            for (int i = 0; i < 4; i++)
#pragma unroll
                for (int j = 0; j < 4; j++)
                    mma_bf16(acc[i][j], al[i], bh[j >> 1][j & 1], bh[j >> 1][2 + (j & 1)]);
        }
        __syncthreads();
    }

    const int er = ln >> 2;
    const int ec = (ln & 3) * 2;
#pragma unroll
    for (int i = 0; i < 4; i++) {
#pragma unroll
        for (int j = 0; j < 4; j++) {
            const int col = n0 + wn + j * 8 + ec;
            const float b0 = __ldg(bias + col), b1 = __ldg(bias + col + 1);
            const int r0 = m0 + wm + i * 16 + er;
            float2 o0 = make_float2(acc[i][j][0] + b0, acc[i][j][1] + b1);
            float2 o1 = make_float2(acc[i][j][2] + b0, acc[i][j][3] + b1);
            *(float2*)(C + (size_t)r0 * N + col) = o0;
            *(float2*)(C + (size_t)(r0 + 8) * N + col) = o1;
        }
    }
}

// ---------------------------------------------------------------------------
// K conversion: qkv fp32 -> Khi/Klo bf16 [b,h,s,d]. (proven R14)
// ---------------------------------------------------------------------------
__global__ __launch_bounds__(256) void convert_k(const float* __restrict__ qkv,
                                                 __nv_bfloat16* __restrict__ khi,
                                                 __nv_bfloat16* __restrict__ klo)
{
    size_t i = (size_t)blockIdx.x * 256 + threadIdx.x;  // over [b][s][h][d4]
    int d4 = i & 15;
    int s  = (i >> 4) & 2047;
    int h  = (i >> 15) & 15;
    int b  = (int)(i >> 19);
    float4 v = *(const float4*)(qkv + ((size_t)(b * Sq + s)) * 3072 + 1024 + h * 64 + d4 * 4);
    uint2 hp, lp;
    split4(v, hp, lp);
    size_t o = (((size_t)(b * Hq + h) * Sq + s) * 64 + d4 * 4);
    *(uint2*)(khi + o) = hp;
    *(uint2*)(klo + o) = lp;
}

// ---------------------------------------------------------------------------
// V transpose: qkv fp32 [b,s,h,d] -> Vt fp16 [b,h,d,s]. (proven R14)
// ---------------------------------------------------------------------------
__global__ __launch_bounds__(128) void convert_vt(const float* __restrict__ qkv,
                                                  __half* __restrict__ vt)
{
    __shared__ __half tile[64][72];
    const int bh = blockIdx.y, b = bh >> 4, h = bh & 15;
    const int s0 = blockIdx.x * 64;
    const int t = threadIdx.x;

#pragma unroll
    for (int i = 0; i < 8; i++) {
        int idx = i * 128 + t;
        int srow = idx >> 4, d4 = idx & 15;
        float4 v = *(const float4*)(qkv + ((size_t)(b * Sq + s0 + srow)) * 3072 + 2048 + h * 64 + d4 * 4);
        tile[d4 * 4 + 0][srow] = __float2half(v.x);
        tile[d4 * 4 + 1][srow] = __float2half(v.y);
        tile[d4 * 4 + 2][srow] = __float2half(v.z);
        tile[d4 * 4 + 3][srow] = __float2half(v.w);
    }
    __syncthreads();

#pragma unroll
    for (int i = 0; i < 4; i++) {
        int idx = i * 128 + t;
        int d = idx >> 3, sg = (idx & 7) * 8;
        uint4 val = *(uint4*)&tile[d][sg];
        *(uint4*)(vt + ((size_t)bh * 64 + d) * Sq + s0 + sg) = val;
    }
}

// ---------------------------------------------------------------------------
// HMMA flash attention (proven R14, unchanged).
// ---------------------------------------------------------------------------
#define AQT 64
#define AKT 64
#define AST 72   // 144 B rows (16B multiple for ldmatrix)

__global__ __launch_bounds__(128) void attn_mma(const float* __restrict__ qkv,
                                                const __nv_bfloat16* __restrict__ khig,
                                                const __nv_bfloat16* __restrict__ klog,
                                                const __half* __restrict__ vtg,
                                                float* __restrict__ ctx)
{
    __shared__ __nv_bfloat16 KQh[AKT * AST], KQl[AKT * AST];
    __shared__ __half VT[64 * AST];
    __shared__ __half Psm[4 * 16 * AST];

    const int t = threadIdx.x, wid = t >> 5, ln = t & 31;
    const int bh = blockIdx.y, b = bh >> 4, h = bh & 15;
    const int q0 = blockIdx.x * AQT;
    const float C1 = 0.125f * 1.44269504f;

    const float* Qg = qkv + ((size_t)(b * Sq + q0)) * 3072 + h * 64;
#pragma unroll
    for (int i = 0; i < 8; i++) {
        int idx = i * 128 + t;
        int row = idx >> 4, c4 = idx & 15;
        float4 v = *(const float4*)(Qg + (size_t)row * 3072 + c4 * 4);
        uint2 hp, lp;
        split4(v, hp, lp);
        *(uint2*)&KQh[row * AST + c4 * 4] = hp;
        *(uint2*)&KQl[row * AST + c4 * 4] = lp;
    }
    __syncthreads();

    const uint32_t sKQh = smem_u32(KQh), sKQl = smem_u32(KQl);
    const uint32_t sVT = smem_u32(VT);
    __half* Pw = Psm + wid * 16 * AST;
    const uint32_t sPw = smem_u32(Pw);

    const int lrow = (ln & 7) + ((ln >> 3) & 1) * 8;
    const int lkc  = (ln >> 4) * 8;
    const int wq   = wid * 16;
    const int er   = ln >> 2;
    const int ec   = (ln & 3) * 2;

    uint32_t qh[4][4], ql[4][4];
#pragma unroll
    for (int c = 0; c < 4; c++) {
        uint32_t a = (uint32_t)(((wq + lrow) * AST + c * 16 + lkc) * 2);
        LDMX4(qh[c][0], qh[c][1], qh[c][2], qh[c][3], sKQh + a);
        LDMX4(ql[c][0], ql[c][1], ql[c][2], ql[c][3], sKQl + a);
    }

    float accd[8][4];
#pragma unroll
    for (int j = 0; j < 8; j++)
#pragma unroll
        for (int f = 0; f < 4; f++) accd[j][f] = 0.f;
    float my0 = -1e30f, my1 = -1e30f, l0 = 0.f, l1 = 0.f;

    const __nv_bfloat16* Khb = khig + (size_t)bh * Sq * 64;
    const __nv_bfloat16* Klb = klog + (size_t)bh * Sq * 64;
    const __half* Vtb = vtg + (size_t)bh * 64 * Sq;

    for (int kt = 0; kt < Sq; kt += AKT) {
        __syncthreads();
#pragma unroll
        for (int i = 0; i < 4; i++) {
            int idx = i * 128 + t;
            int row = idx >> 3, c8 = (idx & 7) * 8;
            *(uint4*)&KQh[row * AST + c8] = *(const uint4*)(Khb + (size_t)(kt + row) * 64 + c8);
            *(uint4*)&KQl[row * AST + c8] = *(const uint4*)(Klb + (size_t)(kt + row) * 64 + c8);
            *(uint4*)&VT[row * AST + c8]  = *(const uint4*)(Vtb + (size_t)row * Sq + kt + c8);
        }
        __syncthreads();

        float s[8][4];
#pragma unroll
        for (int j = 0; j < 8; j++)
#pragma unroll
            for (int f = 0; f < 4; f++) s[j][f] = 0.f;

#pragma unroll
        for (int c = 0; c < 4; c++) {
            uint32_t kh[4][4], kl[4][4];
#pragma unroll
            for (int J = 0; J < 4; J++) {
                uint32_t a = (uint32_t)(((J * 16 + lrow) * AST + c * 16 + lkc) * 2);
                LDMX4(kh[J][0], kh[J][1], kh[J][2], kh[J][3], sKQh + a);
                LDMX4(kl[J][0], kl[J][1], kl[J][2], kl[J][3], sKQl + a);
            }
#pragma unroll
            for (int J = 0; J < 4; J++)
#pragma unroll
                for (int u = 0; u < 2; u++) {
                    int j = 2 * J + u;
                    mma_bf16(s[j], qh[c], kh[J][u], kh[J][2 + u]);
                    mma_bf16(s[j], qh[c], kl[J][u], kl[J][2 + u]);
                    mma_bf16(s[j], ql[c], kh[J][u], kh[J][2 + u]);
                }
        }

        float tm0 = -1e30f, tm1 = -1e30f;
#pragma unroll
        for (int j = 0; j < 8; j++) {
            tm0 = fmaxf(tm0, fmaxf(s[j][0], s[j][1]));
            tm1 = fmaxf(tm1, fmaxf(s[j][2], s[j][3]));
        }
        tm0 *= C1; tm1 *= C1;
        tm0 = fmaxf(tm0, __shfl_xor_sync(0xffffffffu, tm0, 1));
        tm0 = fmaxf(tm0, __shfl_xor_sync(0xffffffffu, tm0, 2));
        tm1 = fmaxf(tm1, __shfl_xor_sync(0xffffffffu, tm1, 1));
        tm1 = fmaxf(tm1, __shfl_xor_sync(0xffffffffu, tm1, 2));
        float mn0 = fmaxf(my0, tm0), mn1 = fmaxf(my1, tm1);
        float corr0 = exp2_fast(my0 - mn0), corr1 = exp2_fast(my1 - mn1);
        my0 = mn0; my1 = mn1;

        float rs0 = 0.f, rs1 = 0.f;
#pragma unroll
        for (int j = 0; j < 8; j++) {
            s[j][0] = exp2_fast(fmaf(s[j][0], C1, -mn0));
            s[j][1] = exp2_fast(fmaf(s[j][1], C1, -mn0));
            s[j][2] = exp2_fast(fmaf(s[j][2], C1, -mn1));
            s[j][3] = exp2_fast(fmaf(s[j][3], C1, -mn1));
            rs0 += s[j][0] + s[j][1];
            rs1 += s[j][2] + s[j][3];
        }
        rs0 += __shfl_xor_sync(0xffffffffu, rs0, 1);
        rs0 += __shfl_xor_sync(0xffffffffu, rs0, 2);
        rs1 += __shfl_xor_sync(0xffffffffu, rs1, 1);
        rs1 += __shfl_xor_sync(0xffffffffu, rs1, 2);
        l0 = l0 * corr0 + rs0;
        l1 = l1 * corr1 + rs1;
#pragma unroll
        for (int j = 0; j < 8; j++) {
            accd[j][0] *= corr0; accd[j][1] *= corr0;
            accd[j][2] *= corr1; accd[j][3] *= corr1;
        }

#pragma unroll
        for (int j = 0; j < 8; j++) {
            __half2 p01 = __floats2half2_rn(s[j][0], s[j][1]);
            __half2 p23 = __floats2half2_rn(s[j][2], s[j][3]);
            *(__half2*)&Pw[er * AST + j * 8 + ec] = p01;
            *(__half2*)&Pw[(er + 8) * AST + j * 8 + ec] = p23;
        }
        __syncwarp();

#pragma unroll
        for (int tt = 0; tt < 4; tt++) {
            uint32_t pa[4];
            uint32_t pad = sPw + (uint32_t)((lrow * AST + tt * 16 + lkc) * 2);
            LDMX4(pa[0], pa[1], pa[2], pa[3], pad);
#pragma unroll
            for (int Jd = 0; Jd < 4; Jd++) {
                uint32_t vh[4];
                uint32_t va = (uint32_t)(((Jd * 16 + lrow) * AST + tt * 16 + lkc) * 2);
                LDMX4(vh[0], vh[1], vh[2], vh[3], sVT + va);
                mma_f16(accd[2 * Jd + 0], pa, vh[0], vh[2]);
                mma_f16(accd[2 * Jd + 1], pa, vh[1], vh[3]);
            }
        }
        __syncwarp();
    }

    const float inv0 = 1.0f / l0, inv1 = 1.0f / l1;
    float* Cb = ctx + (size_t)(b * Sq + q0 + wq) * Eq + h * 64;
#pragma unroll
    for (int j = 0; j < 8; j++) {
        float2 o0 = make_float2(accd[j][0] * inv0, accd[j][1] * inv0);
        float2 o1 = make_float2(accd[j][2] * inv1, accd[j][3] * inv1);
        *(float2*)(Cb + (size_t)er * Eq + 8 * j + ec) = o0;
        *(float2*)(Cb + (size_t)(er + 8) * Eq + 8 * j + ec) = o1;
    }
}

// ---------------------------------------------------------------------------
// Launch
// ---------------------------------------------------------------------------
extern "C" void kernel_launch(void* const* d_in, const int* in_sizes, int n_in,
                              void* d_out, int out_size)
{
    const float* inp   = (const float*)d_in[0];
    const float* qkv_w = (const float*)d_in[1];
    const float* qkv_b = (const float*)d_in[2];
    const float* out_w = (const float*)d_in[3];
    const float* out_b = (const float*)d_in[4];
    float* out = (float*)d_out;

    float* qkv_buf = nullptr;
    float* ctx_buf = nullptr;
    __nv_bfloat16 *khi = nullptr, *klo = nullptr;
    __half* vt = nullptr;
    __nv_bfloat16 *ahi = nullptr, *alo = nullptr;
    __nv_bfloat16 *wqh = nullptr, *wql = nullptr, *woh = nullptr, *wol = nullptr;
    cudaGetSymbolAddress((void**)&qkv_buf, g_qkv);
    cudaGetSymbolAddress((void**)&ctx_buf, g_ctx);
    cudaGetSymbolAddress((void**)&khi, g_khi);
    cudaGetSymbolAddress((void**)&klo, g_klo);
    cudaGetSymbolAddress((void**)&vt, g_vt);
    cudaGetSymbolAddress((void**)&ahi, g_ahi);
    cudaGetSymbolAddress((void**)&alo, g_alo);
    cudaGetSymbolAddress((void**)&wqh, g_wqh);
    cudaGetSymbolAddress((void**)&wql, g_wql);
    cudaGetSymbolAddress((void**)&woh, g_woh);
    cudaGetSymbolAddress((void**)&wol, g_wol);

    cudaFuncSetAttribute(gemm_bf16, cudaFuncAttributeMaxDynamicSharedMemorySize, GSMEM);

    const int M = Bq * Sq; // 8192

    // 0) pre-split inputs and weights
    convert_split<<<(M * Eq) / 4 / 256, 256>>>(inp, ahi, alo);
    convert_split<<<(3 * Eq * Eq) / 4 / 256, 256>>>(qkv_w, wqh, wql);
    convert_split<<<(Eq * Eq) / 4 / 256, 256>>>(out_w, woh, wol);

    // 1) QKV projection
    {
        dim3 grid(3 * Eq / BN, M / BM); // (24, 64)
        gemm_bf16<<<grid, 256, GSMEM>>>(ahi, alo, wqh, wql, qkv_b, qkv_buf, M, 3 * Eq, Eq);
    }
    // 2) K split + V transpose conversion
    {
        convert_k<<<(Bq * Hq * Sq * 16) / 256, 256>>>(qkv_buf, khi, klo);
        dim3 gv(Sq / 64, Bq * Hq);
        convert_vt<<<gv, 128>>>(qkv_buf, vt);
    }
    // 3) Attention
    {
        dim3 grid(Sq / AQT, Bq * Hq); // (32, 64)
        attn_mma<<<grid, 128>>>(qkv_buf, khi, klo, vt, ctx_buf);
    }
    // 4) Output projection (pre-split ctx first)
    {
        convert_split<<<(M * Eq) / 4 / 256, 256>>>(ctx_buf, ahi, alo);
        dim3 grid(Eq / BN, M / BM); // (8, 64)
        gemm_bf16<<<grid, 256, GSMEM>>>(ahi, alo, woh, wol, out_b, out, M, Eq, Eq);
    }
}